// round 4
// baseline (speedup 1.0000x reference)
#include <cuda_runtime.h>
#include <cstdint>

// Triangle_39719857553609:
//   in : decompFE [32768, 2016] f32 (flat strict-lower-triangle, tril(-1) order)
//   out: [32768, 64, 64] f32, symmetric, zero diagonal.
//
// R4: two matrices per 512-thread CTA, all-bulk data movement.
//   2x cp.async.bulk G->S (one mbarrier, 16128 B total)
//   -> build both 64x64 matrices in smem (all 512 threads)
//   -> fence.proxy.async -> 2x cp.async.bulk S->G (32 KB contiguous burst).
// smem ~48 KB -> 4 CTAs/SM x 16 warps = full 64-warp occupancy.

#define NC2        2016
#define ROW_BYTES  (NC2 * 4)            // 8064
#define N_ATOMS    64
#define MAT        (N_ATOMS * N_ATOMS)  // 4096
#define MAT_BYTES  (MAT * 4)            // 16384
#define THREADS    512
#define V4_TOTAL   (2 * MAT / 4)        // 2048 float4 across both matrices

__device__ __forceinline__ uint32_t smem_u32(const void* p) {
    uint32_t a;
    asm("{ .reg .u64 t; cvta.to.shared.u64 t, %1; cvt.u32.u64 %0, t; }"
        : "=r"(a) : "l"(p));
    return a;
}

__global__ __launch_bounds__(THREADS) void triangle_kernel(
    const float* __restrict__ in, float* __restrict__ out)
{
    __shared__ alignas(16) float s_row[2][NC2];    // 16128 B
    __shared__ alignas(16) float s_mat[2][MAT];    // 32768 B
    __shared__ alignas(8)  uint64_t s_mbar;

    const int tid = threadIdx.x;
    const size_t b0 = (size_t)blockIdx.x * 2;      // matrices b0, b0+1

    const uint32_t mbar_a = smem_u32(&s_mbar);

    if (tid == 0)
        asm volatile("mbarrier.init.shared.b64 [%0], 1;" :: "r"(mbar_a) : "memory");
    __syncthreads();

    // ---- issue both bulk loads, single mbarrier expects both rows ----
    if (tid == 0) {
        asm volatile("mbarrier.arrive.expect_tx.shared.b64 _, [%0], %1;"
                     :: "r"(mbar_a), "r"((uint32_t)(2 * ROW_BYTES)) : "memory");
        #pragma unroll
        for (int p = 0; p < 2; p++) {
            const float* src = in + (b0 + p) * NC2;
            const uint32_t dst = smem_u32(s_row[p]);
            asm volatile(
                "cp.async.bulk.shared::cta.global.mbarrier::complete_tx::bytes "
                "[%0], [%1], %2, [%3];"
                :: "r"(dst), "l"(src), "r"((uint32_t)ROW_BYTES), "r"(mbar_a)
                : "memory");
        }
    }

    // all threads wait (parity 0)
    asm volatile(
        "{\n\t"
        ".reg .pred p;\n\t"
        "W_%=:\n\t"
        "mbarrier.try_wait.parity.shared.b64 p, [%0], 0;\n\t"
        "@!p bra W_%=;\n\t"
        "}"
        :: "r"(mbar_a) : "memory");

    // ---- build both symmetric matrices (4 float4 per thread) ----
    #pragma unroll
    for (int q = 0; q < V4_TOTAL / THREADS; q++) {
        const int g4  = tid + q * THREADS;           // 0..2047
        const int p   = g4 >> 10;                    // which matrix
        const int e4  = g4 & 1023;                   // float4 index in matrix
        const int i   = e4 >> 4;                     // row (16 float4/row)
        const int j0  = (e4 & 15) << 2;
        const int tri_i = (i * (i - 1)) >> 1;
        const float* __restrict__ r = s_row[p];

        float4 v;
        float* vp = reinterpret_cast<float*>(&v);
        #pragma unroll
        for (int mI = 0; mI < 4; mI++) {
            const int j = j0 + mI;
            float val;
            if (j < i)       val = r[tri_i + j];                 // lower
            else if (j > i)  val = r[((j * (j - 1)) >> 1) + i];  // upper
            else             val = 0.0f;                         // diag
            vp[mI] = val;
        }
        reinterpret_cast<float4*>(s_mat[p])[e4] = v;
    }
    __syncthreads();

    // ---- two 16 KB bulk stores = one 32 KB contiguous burst ----
    if (tid == 0) {
        asm volatile("fence.proxy.async.shared::cta;" ::: "memory");
        #pragma unroll
        for (int p = 0; p < 2; p++) {
            float* dst = out + (b0 + p) * MAT;
            const uint32_t src = smem_u32(s_mat[p]);
            asm volatile(
                "cp.async.bulk.global.shared::cta.bulk_group [%0], [%1], %2;"
                :: "l"(dst), "r"(src), "r"((uint32_t)MAT_BYTES)
                : "memory");
        }
        asm volatile("cp.async.bulk.commit_group;" ::: "memory");
        asm volatile("cp.async.bulk.wait_group 0;" ::: "memory");
    }
}

extern "C" void kernel_launch(void* const* d_in, const int* in_sizes, int n_in,
                              void* d_out, int out_size)
{
    const float* decompFE = (const float*)d_in[0];
    float* out = (float*)d_out;

    const int batch = in_sizes[0] / NC2;   // 32768
    triangle_kernel<<<batch / 2, THREADS>>>(decompFE, out);
}